// round 8
// baseline (speedup 1.0000x reference)
#include <cuda_runtime.h>
#include <cstdint>

#define DEVI __device__ __forceinline__

// Problem constants
static constexpr int B_TOT  = 16384;
static constexpr int F_DIM  = 50;
static constexpr int E_DIM  = 64;
static constexpr int D_DIM  = 128;
static constexpr int FE     = F_DIM * E_DIM;      // 3200 floats per batch

// Kernel config: 3 CTAs/SM, 256 threads (8 warps), 1 batch per CTA-iteration
static constexpr int NTHREADS = 256;
static constexpr int GRID     = 456;              // 3 CTAs per SM on GB300 (152 SMs)
static constexpr int NGI      = B_TOT;            // one batch per iteration

// SMEM map (u32 units)
// A-frag table: [w(8)][s(4)][lane(32)][reg(4)]  (f16x2, exact m16n8k16 frag order)
static constexpr int AFRAG_U32 = 8 * 4 * 32 * 4;              // 4096 (16 KB)
// x16: B fragments in frag order: [buf(2)][s(4)][lane(32)][20]  (16 used + 4 pad)
static constexpr int X16_LSTR  = 20;                          // u32 per lane slot
static constexpr int X16_SBLK  = 32 * X16_LSTR;               // 640
static constexpr int X16_BUF   = 4 * X16_SBLK;                // 2560 u32 (10 KB)
static constexpr int X16_OFF   = AFRAG_U32;                   // 4096
// fp32 staging: [buf(2)][f(50)][stride 68]
static constexpr int ST_STR    = 68;
static constexpr int ST_BUF    = F_DIM * ST_STR;              // 3400 floats
static constexpr int ST_OFF    = X16_OFF + 2 * X16_BUF;       // 9216
static constexpr int SMEM_U32  = ST_OFF + 2 * ST_BUF;         // 16016
static constexpr int SMEM_BYTES = SMEM_U32 * 4;               // 64064 B (3 CTAs/SM fit)

// ---------------------------------------------------------------------------
DEVI uint32_t smem_u32(const void* p) {
    uint32_t a;
    asm("{ .reg .u64 t; cvta.to.shared.u64 t, %1; cvt.u32.u64 %0, t; }" : "=r"(a) : "l"(p));
    return a;
}
DEVI uint32_t pack_h2(float lo, float hi) {
    uint32_t r;
    asm("cvt.rn.f16x2.f32 %0, %1, %2;" : "=r"(r) : "f"(hi), "f"(lo));
    return r;
}
DEVI void mma16n8k16(float& c0, float& c1, float& c2, float& c3,
                     uint32_t a0, uint32_t a1, uint32_t a2, uint32_t a3,
                     uint32_t b0, uint32_t b1) {
    asm volatile(
        "mma.sync.aligned.m16n8k16.row.col.f32.f16.f16.f32 "
        "{%0,%1,%2,%3}, {%4,%5,%6,%7}, {%8,%9}, {%0,%1,%2,%3};"
        : "+f"(c0), "+f"(c1), "+f"(c2), "+f"(c3)
        : "r"(a0), "r"(a1), "r"(a2), "r"(a3), "r"(b0), "r"(b1));
}
DEVI void cp_async16(uint32_t dst, const void* src) {
    asm volatile("cp.async.cg.shared.global [%0], [%1], 16;" :: "r"(dst), "l"(src));
}
DEVI void cp_commit()  { asm volatile("cp.async.commit_group;" ::: "memory"); }
DEVI void cp_wait1()   { asm volatile("cp.async.wait_group 1;" ::: "memory"); }

// Prefetch one batch (3200 floats = 800 16B chunks) into stage[buf], stride 68
DEVI void prefetch(uint32_t stage_addr, const float* __restrict__ gb, int buf, int tid) {
    const uint32_t dbase = stage_addr + (uint32_t)(buf * ST_BUF) * 4u;
#pragma unroll 1
    for (int c = tid; c < 800; c += NTHREADS) {
        int f = c >> 4, seg = c & 15;
        cp_async16(dbase + (uint32_t)(f * ST_STR + seg * 4) * 4u, gb + f * E_DIM + seg * 4);
    }
}

// ---------------------------------------------------------------------------
__global__ void __launch_bounds__(NTHREADS, 3)
InnerProduct_65429531787441_kernel(const float* __restrict__ X,
                                   const float* __restrict__ Th,
                                   float* __restrict__ out) {
    extern __shared__ uint32_t smu[];
    uint32_t* afr   = smu;                           // A-frag table
    uint32_t* x16   = smu + X16_OFF;                 // B-frag tile (2 buffers)
    float*    stage = reinterpret_cast<float*>(smu + ST_OFF);
    const uint32_t stage_addr = smem_u32(stage);

    const int tid  = threadIdx.x;
    const int lane = tid & 31;
    const int w    = tid >> 5;       // warp 0..7 -> d block [w*16, w*16+16)
    const int lg   = lane >> 2;      // 0..7
    const int lq   = lane & 3;       // 0..3

    // Prologue prefetch (iteration 0 -> stage buffer 0)
    const int gi0 = blockIdx.x;
    prefetch(stage_addr, X + (size_t)gi0 * FE, 0, tid);
    cp_commit();

    // Build A-frag table (Theta fp16 pairs, m16n8k16 frag order, zero-pad f>=50)
    for (int i = tid; i < AFRAG_U32; i += NTHREADS) {
        int j   = i & 3;
        int ln  = (i >> 2) & 31;
        int s   = (i >> 7) & 3;
        int ww  = i >> 9;
        int row = ww * 16 + (j & 1) * 8 + (ln >> 2);
        int k0  = 16 * s + 2 * (ln & 3) + (j >> 1) * 8;
        float v0 = (k0     < F_DIM) ? Th[row * F_DIM + k0]     : 0.f;
        float v1 = (k0 + 1 < F_DIM) ? Th[row * F_DIM + k0 + 1] : 0.f;
        afr[i] = pack_h2(v0, v1);
    }
    __syncthreads();

    const uint4* afr4 = reinterpret_cast<const uint4*>(afr);
    const uint4* x16r = reinterpret_cast<const uint4*>(x16);

    // Convert-pass role: warp w handles s = w&3, e-half = w>>2
    const int cs   = w & 3;
    const int half = w >> 2;

    int it = 0;
    for (int gi = gi0; gi < NGI; gi += GRID, ++it) {
        const int buf = it & 1;

        // Prefetch next batch into the other staging buffer, then wait for current
        if (gi + GRID < NGI) prefetch(stage_addr, X + (size_t)(gi + GRID) * FE, buf ^ 1, tid);
        cp_commit();            // empty tail group keeps wait semantics correct
        cp_wait1();
        __syncthreads();        // stage[buf] visible to all threads

        // Convert: stage fp32 -> x16 f16x2 in exact B-fragment order.
        // Thread (cs, half, lane): 2 uint4, covering ni pairs (4*half+0,1) and (4*half+2,3)
        {
            const float* st = stage + buf * ST_BUF;
            uint32_t* xw = x16 + buf * X16_BUF + cs * X16_SBLK + lane * X16_LSTR;
            const int f0 = 16 * cs + 2 * lq;
            if (cs < 3) {       // all f < 50: unpredicated
#pragma unroll
                for (int p = 0; p < 2; p++) {
                    const int e0 = (half * 4 + 2 * p) * 8 + lg;
                    uint4 q;
                    q.x = pack_h2(st[f0 * ST_STR + e0],       st[(f0 + 1) * ST_STR + e0]);
                    q.y = pack_h2(st[(f0 + 8) * ST_STR + e0], st[(f0 + 9) * ST_STR + e0]);
                    q.z = pack_h2(st[f0 * ST_STR + e0 + 8],       st[(f0 + 1) * ST_STR + e0 + 8]);
                    q.w = pack_h2(st[(f0 + 8) * ST_STR + e0 + 8], st[(f0 + 9) * ST_STR + e0 + 8]);
                    *reinterpret_cast<uint4*>(xw + (half * 2 + p) * 4) = q;
                }
            } else {            // s = 3: f in 48..63, predicate f >= 50 to zero
#pragma unroll
                for (int p = 0; p < 2; p++) {
                    const int e0 = (half * 4 + 2 * p) * 8 + lg;
                    float v00 = (f0     < F_DIM) ? st[f0 * ST_STR + e0]       : 0.f;
                    float v01 = (f0 + 1 < F_DIM) ? st[(f0 + 1) * ST_STR + e0] : 0.f;
                    float v02 = (f0     < F_DIM) ? st[f0 * ST_STR + e0 + 8]       : 0.f;
                    float v03 = (f0 + 1 < F_DIM) ? st[(f0 + 1) * ST_STR + e0 + 8] : 0.f;
                    uint4 q;
                    q.x = pack_h2(v00, v01);
                    q.y = 0u;   // f0+8, f0+9 in 56..63 -> always zero
                    q.z = pack_h2(v02, v03);
                    q.w = 0u;
                    *reinterpret_cast<uint4*>(xw + (half * 2 + p) * 4) = q;
                }
            }
        }
        __syncthreads();        // x16[buf] ready

        // MMA: warp computes proj rows [w*16, w*16+16) x all 64 e
        float acc[8][4];
#pragma unroll
        for (int ni = 0; ni < 8; ni++)
#pragma unroll
            for (int j = 0; j < 4; j++) acc[ni][j] = 0.f;

        const uint4* xb = x16r + buf * (X16_BUF / 4);
#pragma unroll
        for (int s = 0; s < 4; s++) {
            const uint4 Aq = afr4[(w * 4 + s) * 32 + lane];
            const uint4* bl = xb + s * (X16_SBLK / 4) + lane * (X16_LSTR / 4);
            const uint4 B0 = bl[0];
            const uint4 B1 = bl[1];
            const uint4 B2 = bl[2];
            const uint4 B3 = bl[3];
            mma16n8k16(acc[0][0], acc[0][1], acc[0][2], acc[0][3], Aq.x, Aq.y, Aq.z, Aq.w, B0.x, B0.y);
            mma16n8k16(acc[1][0], acc[1][1], acc[1][2], acc[1][3], Aq.x, Aq.y, Aq.z, Aq.w, B0.z, B0.w);
            mma16n8k16(acc[2][0], acc[2][1], acc[2][2], acc[2][3], Aq.x, Aq.y, Aq.z, Aq.w, B1.x, B1.y);
            mma16n8k16(acc[3][0], acc[3][1], acc[3][2], acc[3][3], Aq.x, Aq.y, Aq.z, Aq.w, B1.z, B1.w);
            mma16n8k16(acc[4][0], acc[4][1], acc[4][2], acc[4][3], Aq.x, Aq.y, Aq.z, Aq.w, B2.x, B2.y);
            mma16n8k16(acc[5][0], acc[5][1], acc[5][2], acc[5][3], Aq.x, Aq.y, Aq.z, Aq.w, B2.z, B2.w);
            mma16n8k16(acc[6][0], acc[6][1], acc[6][2], acc[6][3], Aq.x, Aq.y, Aq.z, Aq.w, B3.x, B3.y);
            mma16n8k16(acc[7][0], acc[7][1], acc[7][2], acc[7][3], Aq.x, Aq.y, Aq.z, Aq.w, B3.z, B3.w);
        }

        // Epilogue: sum of squares over all 64 e, quad shfl reduce, direct store
        {
            float a = 0.f, b = 0.f;
#pragma unroll
            for (int ni = 0; ni < 8; ni++) {
                a = fmaf(acc[ni][0], acc[ni][0], a);
                a = fmaf(acc[ni][1], acc[ni][1], a);
                b = fmaf(acc[ni][2], acc[ni][2], b);
                b = fmaf(acc[ni][3], acc[ni][3], b);
            }
            a += __shfl_xor_sync(0xffffffffu, a, 1);
            a += __shfl_xor_sync(0xffffffffu, a, 2);
            b += __shfl_xor_sync(0xffffffffu, b, 1);
            b += __shfl_xor_sync(0xffffffffu, b, 2);
            if (lq == 0) {
                float* orow = out + (size_t)gi * D_DIM;
                orow[w * 16 + lg]     = a;
                orow[w * 16 + lg + 8] = b;
            }
        }
        // No trailing barrier: next iteration's post-wait sync orders x16/stage reuse.
    }
}

extern "C" void kernel_launch(void* const* d_in, const int* in_sizes, int n_in,
                              void* d_out, int out_size) {
    (void)in_sizes; (void)n_in; (void)out_size;
    const float* X  = (const float*)d_in[0];
    const float* Th = (const float*)d_in[1];
    float* out = (float*)d_out;
    cudaFuncSetAttribute(InnerProduct_65429531787441_kernel,
                         cudaFuncAttributeMaxDynamicSharedMemorySize, SMEM_BYTES);
    InnerProduct_65429531787441_kernel<<<GRID, NTHREADS, SMEM_BYTES>>>(X, Th, out);
}

// round 10
// speedup vs baseline: 1.2278x; 1.2278x over previous
#include <cuda_runtime.h>
#include <cstdint>

#define DEVI __device__ __forceinline__

// Problem constants
static constexpr int B_TOT  = 16384;
static constexpr int F_DIM  = 50;
static constexpr int E_DIM  = 64;
static constexpr int D_DIM  = 128;
static constexpr int FE     = F_DIM * E_DIM;      // 3200 floats per batch

// Kernel config: 2 CTAs/SM, 256 threads (8 warps), 2 batches per CTA-iteration
static constexpr int NTHREADS = 256;
static constexpr int GRID     = 304;
static constexpr int BPI      = 2;
static constexpr int NGI      = B_TOT / BPI;      // 8192 groups

// fp16 tile: [f2 rows 0..31][e 64] stride 72 (rows 25..31 zero pad)
static constexpr int F2_REAL   = 25;
static constexpr int X16_STR   = 72;
static constexpr int X16_BATCH = 32 * X16_STR;               // 2304 u32
static constexpr int X16_BUF   = BPI * X16_BATCH;            // 4608 u32

// A-frag table: [mq(4)][s(4)][mi(2)][lane(32)][reg(4)] u32 (f16x2, frag order)
static constexpr int AFRAG_U32 = 4 * 4 * 2 * 32 * 4;         // 4096

// fp32 staging: [buf(2)][group: 2 batches x 3200 floats] (linear copy of gmem)
static constexpr int ST_GRP    = BPI * FE;                   // 6400 floats

// SMEM map (u32)
static constexpr int X16_OFF   = AFRAG_U32;                  // 4096
static constexpr int ST_OFF    = X16_OFF + 2 * X16_BUF;      // 13312
static constexpr int SMEM_U32  = ST_OFF + 2 * ST_GRP;        // 26112
static constexpr int SMEM_BYTES = SMEM_U32 * 4;              // 104448 B (2 CTAs/SM)

// Pairs per group for the owned prefetch/convert chain: b(2) x f2(25) x seg(16)
static constexpr int NPAIRS = BPI * F2_REAL * 16;            // 800

// ---------------------------------------------------------------------------
DEVI uint32_t smem_u32(const void* p) {
    uint32_t a;
    asm("{ .reg .u64 t; cvta.to.shared.u64 t, %1; cvt.u32.u64 %0, t; }" : "=r"(a) : "l"(p));
    return a;
}
DEVI uint32_t pack_h2(float lo, float hi) {
    uint32_t r;
    asm("cvt.rn.f16x2.f32 %0, %1, %2;" : "=r"(r) : "f"(hi), "f"(lo));
    return r;
}
DEVI void mma16n8k16(float& c0, float& c1, float& c2, float& c3,
                     uint32_t a0, uint32_t a1, uint32_t a2, uint32_t a3,
                     uint32_t b0, uint32_t b1) {
    asm volatile(
        "mma.sync.aligned.m16n8k16.row.col.f32.f16.f16.f32 "
        "{%0,%1,%2,%3}, {%4,%5,%6,%7}, {%8,%9}, {%0,%1,%2,%3};"
        : "+f"(c0), "+f"(c1), "+f"(c2), "+f"(c3)
        : "r"(a0), "r"(a1), "r"(a2), "r"(a3), "r"(b0), "r"(b1));
}
DEVI void cp_async16(uint32_t dst, const void* src) {
    asm volatile("cp.async.cg.shared.global [%0], [%1], 16;" :: "r"(dst), "l"(src) : "memory");
}
DEVI void cp_commit()  { asm volatile("cp.async.commit_group;" ::: "memory"); }
DEVI void cp_wait1()   { asm volatile("cp.async.wait_group 1;" ::: "memory"); }

// Owned prefetch: thread copies BOTH chunks (rows 2f2, 2f2+1 at seg) of its pairs.
DEVI void prefetch(uint32_t stage_addr, const float* __restrict__ gb, int buf, int tid) {
    const uint32_t dbase = stage_addr + (uint32_t)(buf * ST_GRP) * 4u;
#pragma unroll 1
    for (int p = tid; p < NPAIRS; p += NTHREADS) {
        int b   = p / 400;
        int r   = p - b * 400;
        int f2  = r >> 4;
        int seg = r & 15;
        int off = b * FE + (2 * f2) * E_DIM + seg * 4;
        cp_async16(dbase + (uint32_t)off * 4u,           gb + off);
        cp_async16(dbase + (uint32_t)(off + E_DIM) * 4u, gb + off + E_DIM);
    }
}

// Owned convert: thread converts exactly the pairs it prefetched (no barrier needed).
DEVI void convert(uint32_t* __restrict__ x16dst, const float* __restrict__ st, int tid) {
#pragma unroll 1
    for (int p = tid; p < NPAIRS; p += NTHREADS) {
        int b   = p / 400;
        int r   = p - b * 400;
        int f2  = r >> 4;
        int seg = r & 15;
        const float* p0 = st + b * FE + (2 * f2) * E_DIM + seg * 4;
        float4 lo = *reinterpret_cast<const float4*>(p0);
        float4 hi = *reinterpret_cast<const float4*>(p0 + E_DIM);
        uint4 q;
        q.x = pack_h2(lo.x, hi.x);
        q.y = pack_h2(lo.y, hi.y);
        q.z = pack_h2(lo.z, hi.z);
        q.w = pack_h2(lo.w, hi.w);
        *reinterpret_cast<uint4*>(x16dst + b * X16_BATCH + f2 * X16_STR + seg * 4) = q;
    }
}

// ---------------------------------------------------------------------------
__global__ void __launch_bounds__(NTHREADS, 2)
InnerProduct_65429531787441_kernel(const float* __restrict__ X,
                                   const float* __restrict__ Th,
                                   float* __restrict__ out) {
    extern __shared__ uint32_t smu[];
    uint32_t* afr   = smu;                           // A-frag table (f16x2)
    uint32_t* x16   = smu + X16_OFF;                 // fp16 B tile (2 buffers)
    float*    stage = reinterpret_cast<float*>(smu + ST_OFF);
    const uint32_t stage_addr = smem_u32(stage);

    const int tid  = threadIdx.x;
    const int lane = tid & 31;
    const int w    = tid >> 5;
    const int b_l  = w >> 2;        // batch slot 0..1
    const int mq   = w & 3;         // d quarter
    const int lg   = lane >> 2;     // 0..7
    const int lq   = lane & 3;      // 0..3

    const int gi0 = blockIdx.x;

    // Prologue: prefetch groups gi0 (buf 0) and gi0+GRID (buf 1)
    prefetch(stage_addr, X + (size_t)gi0 * ST_GRP, 0, tid);
    cp_commit();
    if (gi0 + GRID < NGI)
        prefetch(stage_addr, X + (size_t)(gi0 + GRID) * ST_GRP, 1, tid);
    cp_commit();

    // Build A-frag table (Theta fp16 pairs, m16n8k16 frag order, zero-pad f>=50)
    for (int i = tid; i < AFRAG_U32; i += NTHREADS) {
        int j   = i & 3;
        int ln  = (i >> 2) & 31;
        int mi  = (i >> 7) & 1;
        int s   = (i >> 8) & 3;
        int mq_ = i >> 10;
        int row = mq_ * 32 + mi * 16 + (j & 1) * 8 + (ln >> 2);
        int k0  = 16 * s + 2 * (ln & 3) + (j >> 1) * 8;
        float v0 = (k0     < F_DIM) ? Th[row * F_DIM + k0]     : 0.f;
        float v1 = (k0 + 1 < F_DIM) ? Th[row * F_DIM + k0 + 1] : 0.f;
        afr[i] = pack_h2(v0, v1);
    }
    // Zero pad f2-rows 25..31 in all 4 (buf, batch) slots (stable forever)
    for (int i = tid; i < 2 * BPI * (32 - F2_REAL) * X16_STR; i += NTHREADS) {
        int slot = i / ((32 - F2_REAL) * X16_STR);
        int r    = i % ((32 - F2_REAL) * X16_STR);
        x16[slot * X16_BATCH + F2_REAL * X16_STR + r] = 0u;
    }

    cp_wait1();                     // group gi0 complete (own copies visible)
    convert(x16, stage, tid);       // group gi0 -> x16[0]
    __syncthreads();                // publish A table, pads, x16[0]

    const uint4* afr4 = reinterpret_cast<const uint4*>(afr);

    int it = 0;
    for (int gi = gi0; gi < NGI; gi += GRID, ++it) {
        const int buf = it & 1;

        // Prefetch group gi+2*GRID into stage[buf] (its old content was
        // converted by this same thread last iteration -> safe overwrite).
        if (gi + 2 * GRID < NGI)
            prefetch(stage_addr, X + (size_t)(gi + 2 * GRID) * ST_GRP, buf, tid);
        cp_commit();
        cp_wait1();                 // group gi+GRID complete (own copies)

        // Convert next group into the other x16 buffer (consumed next iter).
        if (gi + GRID < NGI)
            convert(x16 + (buf ^ 1) * X16_BUF, stage + (buf ^ 1) * ST_GRP, tid);

        // MMA on current group from x16[buf] (published by last barrier).
        const uint32_t* xb = x16 + buf * X16_BUF + b_l * X16_BATCH;

        float acc[2][8][4];
#pragma unroll
        for (int mi = 0; mi < 2; mi++)
#pragma unroll
            for (int ni = 0; ni < 8; ni++)
#pragma unroll
                for (int j = 0; j < 4; j++) acc[mi][ni][j] = 0.f;

#pragma unroll
        for (int s = 0; s < 4; s++) {
            uint4 A0 = afr4[((mq * 4 + s) * 2 + 0) * 32 + lane];
            uint4 A1 = afr4[((mq * 4 + s) * 2 + 1) * 32 + lane];
            const int f2a = 8 * s + lq;
            uint32_t Bf[8][2];
#pragma unroll
            for (int ni = 0; ni < 8; ni++) {
                const int e = ni * 8 + lg;
                Bf[ni][0] = xb[f2a * X16_STR + e];
                Bf[ni][1] = xb[(f2a + 4) * X16_STR + e];
            }
#pragma unroll
            for (int ni = 0; ni < 8; ni++) {
                mma16n8k16(acc[0][ni][0], acc[0][ni][1], acc[0][ni][2], acc[0][ni][3],
                           A0.x, A0.y, A0.z, A0.w, Bf[ni][0], Bf[ni][1]);
                mma16n8k16(acc[1][ni][0], acc[1][ni][1], acc[1][ni][2], acc[1][ni][3],
                           A1.x, A1.y, A1.z, A1.w, Bf[ni][0], Bf[ni][1]);
            }
        }

        // Epilogue: sum of squares over this warp's full e-range, shfl, store
        float* orow = out + (size_t)(gi * BPI + b_l) * D_DIM;
#pragma unroll
        for (int mi = 0; mi < 2; mi++) {
            float a = 0.f, b = 0.f;
#pragma unroll
            for (int ni = 0; ni < 8; ni++) {
                a = fmaf(acc[mi][ni][0], acc[mi][ni][0], a);
                a = fmaf(acc[mi][ni][1], acc[mi][ni][1], a);
                b = fmaf(acc[mi][ni][2], acc[mi][ni][2], b);
                b = fmaf(acc[mi][ni][3], acc[mi][ni][3], b);
            }
            a += __shfl_xor_sync(0xffffffffu, a, 1);
            a += __shfl_xor_sync(0xffffffffu, a, 2);
            b += __shfl_xor_sync(0xffffffffu, b, 1);
            b += __shfl_xor_sync(0xffffffffu, b, 2);
            if (lq == 0) {
                const int d = mq * 32 + mi * 16 + lg;
                orow[d]     = a;
                orow[d + 8] = b;
            }
        }

        __syncthreads();   // single barrier: publish x16[buf^1], close x16[buf] reads
    }
}

extern "C" void kernel_launch(void* const* d_in, const int* in_sizes, int n_in,
                              void* d_out, int out_size) {
    (void)in_sizes; (void)n_in; (void)out_size;
    const float* X  = (const float*)d_in[0];
    const float* Th = (const float*)d_in[1];
    float* out = (float*)d_out;
    cudaFuncSetAttribute(InnerProduct_65429531787441_kernel,
                         cudaFuncAttributeMaxDynamicSharedMemorySize, SMEM_BYTES);
    InnerProduct_65429531787441_kernel<<<GRID, NTHREADS, SMEM_BYTES>>>(X, Th, out);
}